// round 3
// baseline (speedup 1.0000x reference)
#include <cuda_runtime.h>

#define BATCH 16384
#define NNZ   819200
#define KDIM  16
#define VOCAB 1000000

__device__ int g_row_ptr[BATCH + 1];
__device__ int g_is64;

// ---------------------------------------------------------------------------
// Detection: interpret buffer as 32-bit words. Words 2i+1 (i < NNZ/2) are
// in-bounds under BOTH dtype views. int64 view: high words == 0. int32 view:
// sorted index values near position NNZ-16 are ~16383 != 0.
// ---------------------------------------------------------------------------
__device__ __forceinline__ int detect_is64(const unsigned int* __restrict__ w) {
    unsigned int acc = 0;
    int base = NNZ / 2 - 8;
#pragma unroll
    for (int i = 0; i < 8; i++) acc |= w[2 * (base + i) + 1];
    return (acc == 0u) ? 1 : 0;
}

// ---------------------------------------------------------------------------
// K1: row_ptr[b] = lower_bound(index, b). One thread per boundary; a single
// fully-parallel wave (~3.5 warps/SM) pays the 20-probe chain exactly once.
// ---------------------------------------------------------------------------
__global__ void __launch_bounds__(256)
rowptr_kernel(const void* __restrict__ index) {
    int b = blockIdx.x * blockDim.x + threadIdx.x;
    if (b > BATCH) return;

    int is64 = detect_is64((const unsigned int*)index);
    if (b == 0) g_is64 = is64;

    int lo = 0, hi = NNZ;
    if (is64) {
        const long long* idx = (const long long*)index;
        const long long t = (long long)b;
        while (lo < hi) {
            int mid = (lo + hi) >> 1;
            if (__ldg(idx + mid) < t) lo = mid + 1; else hi = mid;
        }
    } else {
        const int* idx = (const int*)index;
        while (lo < hi) {
            int mid = (lo + hi) >> 1;
            if (__ldg(idx + mid) < b) lo = mid + 1; else hi = mid;
        }
    }
    g_row_ptr[b] = lo;
}

// ---------------------------------------------------------------------------
// K2: warp per batch row. Chunks of 32 nonzeros:
//  - coalesced (feat, value) loads, prefetched one chunk ahead
//  - per-lane first-order gather (one instruction for 32 nnz)
//  - 8 groups x 4 lanes: each LDG.128 retires 8 embedding rows
//  - butterfly epilogue, no atomics
// ---------------------------------------------------------------------------
__device__ __forceinline__ float warp_sum(float r) {
#pragma unroll
    for (int o = 16; o > 0; o >>= 1)
        r += __shfl_xor_sync(0xffffffffu, r, o);
    return r;
}

template <bool IS64>
__device__ __forceinline__ int load_feat(const void* __restrict__ p, int i) {
    if (IS64) return (int)__ldg((const long long*)p + i);
    return __ldg((const int*)p + i);
}

template <bool IS64>
__device__ __forceinline__ float fm_row_accum(
        int s, int e, int lane,
        const void* __restrict__ feats,
        const float* __restrict__ values,
        const float* __restrict__ weights,
        const float* __restrict__ embedding) {
    const int g = lane >> 2;   // which nonzero within an octet
    const int m = lane & 3;    // float4 slot: k = 4m .. 4m+3

    float4 t1 = make_float4(0.f, 0.f, 0.f, 0.f);
    float  t2 = 0.f, first = 0.f;

    int   j = s + lane;
    int   f = 0;
    float v = 0.f;
    if (j < e) { f = load_feat<IS64>(feats, j); v = __ldg(values + j); }

    for (int base = s; base < e; base += 32) {
        const int   f_cur = f;
        const float v_cur = v;
        // prefetch next chunk's (feat, value) before dependent work
        const int jn = j + 32;
        if (jn < e) { f = load_feat<IS64>(feats, jn); v = __ldg(values + jn); }
        else        { f = 0; v = 0.f; }
        j = jn;

        first += __ldg(weights + f_cur) * v_cur;

        const int frow = f_cur * KDIM;
#pragma unroll
        for (int t = 0; t < 4; t++) {
            const int   src = 8 * t + g;
            const int   fr  = __shfl_sync(0xffffffffu, frow,  src);
            const float vv  = __shfl_sync(0xffffffffu, v_cur, src);
            const float4 ev4 = __ldg((const float4*)(embedding + fr) + m);
            const float e0 = ev4.x * vv, e1 = ev4.y * vv,
                        e2 = ev4.z * vv, e3 = ev4.w * vv;
            t1.x += e0; t1.y += e1; t1.z += e2; t1.w += e3;
            t2   += e0 * e0 + e1 * e1 + e2 * e2 + e3 * e3;
        }
    }

    // sum t1 over the 8 groups (group bits = lane bits 2..4)
#pragma unroll
    for (int o = 4; o <= 16; o <<= 1) {
        t1.x += __shfl_xor_sync(0xffffffffu, t1.x, o);
        t1.y += __shfl_xor_sync(0xffffffffu, t1.y, o);
        t1.z += __shfl_xor_sync(0xffffffffu, t1.z, o);
        t1.w += __shfl_xor_sync(0xffffffffu, t1.w, o);
    }

    // 8 lane-replicas per m-slot hold the full t1_k for their 4 ks;
    // 32-lane sum counts each k 8x -> coefficient 0.5/8 = 0.0625.
    float r = 0.0625f * (t1.x * t1.x + t1.y * t1.y + t1.z * t1.z + t1.w * t1.w)
            - 0.5f * t2 + first;
    return warp_sum(r);
}

__global__ void __launch_bounds__(256)
fm_kernel(const void* __restrict__ feats,
          const float* __restrict__ values,
          const float* __restrict__ weights,
          const float* __restrict__ embedding,
          const float* __restrict__ bias,
          float* __restrict__ out) {
    const int warp = (blockIdx.x * blockDim.x + threadIdx.x) >> 5;
    const int lane = threadIdx.x & 31;
    if (warp >= BATCH) return;
    const int b = warp;

    const int is64 = g_is64;
    int se = 0;
    if (lane < 2) se = g_row_ptr[b + lane];
    const int s = __shfl_sync(0xffffffffu, se, 0);
    const int e = __shfl_sync(0xffffffffu, se, 1);

    float r;
    if (is64) r = fm_row_accum<true >(s, e, lane, feats, values, weights, embedding);
    else      r = fm_row_accum<false>(s, e, lane, feats, values, weights, embedding);

    if (lane == 0) {
        const float x = r + __ldg(bias);
        out[b] = 1.0f / (1.0f + expf(-x));
    }
}

// ---------------------------------------------------------------------------
extern "C" void kernel_launch(void* const* d_in, const int* in_sizes, int n_in,
                              void* d_out, int out_size) {
    const void*  index_p   = nullptr;
    const void*  feats_p   = nullptr;
    const float* values_p  = nullptr;
    const float* bias_p    = nullptr;
    const float* weights_p = nullptr;
    const float* embed_p   = nullptr;

    int triple = 0;
    for (int i = 0; i < n_in; i++) {
        int sz = in_sizes[i];
        if (sz == NNZ) {
            if      (triple == 0) index_p  = d_in[i];
            else if (triple == 1) feats_p  = d_in[i];
            else                  values_p = (const float*)d_in[i];
            triple++;
        } else if (sz == VOCAB) {
            weights_p = (const float*)d_in[i];
        } else if (sz == VOCAB * KDIM) {
            embed_p = (const float*)d_in[i];
        } else if (sz == 1) {
            bias_p = (const float*)d_in[i];   // last size-1 input is bias
        }
    }

    float* out = (float*)d_out;
    (void)out_size;

    rowptr_kernel<<<(BATCH + 1 + 255) / 256, 256>>>(index_p);
    fm_kernel<<<(BATCH * 32 + 255) / 256, 256>>>(feats_p, values_p, weights_p,
                                                 embed_p, bias_p, out);
}